// round 1
// baseline (speedup 1.0000x reference)
#include <cuda_runtime.h>
#include <cuda_bf16.h>
#include <math.h>

// Problem constants (fixed shapes)
#define D_MODEL 2048
#define KBANDS  64
#define WWIN    512
#define STRIDE  256
#define NCHUNK  32
#define SEQ     8192
#define NRET    8

#define BN 32     // n-tile per smem stage
#define BD 128    // d-tile per block

// ---------------- scratch (device globals; no allocation allowed) ------------
__device__ float g_coeffs[NCHUNK * KBANDS * D_MODEL];  // 16 MB
__device__ float g_norms[NCHUNK * KBANDS];
__device__ float g_T[KBANDS * D_MODEL];
__device__ float g_vr[D_MODEL];
__device__ float g_vi[D_MODEL];
__device__ float g_cnorms[KBANDS];
__device__ float g_delta[KBANDS];
__device__ float g_ctx[D_MODEL];

// ---------------- packed f32x2 helpers (sm_103a FFMA2) -----------------------
__device__ __forceinline__ void fma2(unsigned long long& d,
                                     unsigned long long a,
                                     unsigned long long b) {
    asm("fma.rn.f32x2 %0, %1, %2, %0;" : "+l"(d) : "l"(a), "l"(b));
}
__device__ __forceinline__ float2 unpack2(unsigned long long p) {
    unsigned int lo, hi;
    asm("mov.b64 {%0, %1}, %2;" : "=r"(lo), "=r"(hi) : "l"(p));
    return make_float2(__uint_as_float(lo), __uint_as_float(hi));
}

// ---------------- K1: fused h_mean + Chebyshev GEMM --------------------------
// coeffs[i,k,d] = (2/W) * sum_n cheby[k,n] * data_i[n,d], row k=0 halved.
// data_i rows: n<256 -> (i==0 ? buf[256+n] : hmean[(i-1)*256+n]); n>=256 -> hmean[(i-1)*256+n]
// hmean[r,d] = 0.5*(scan0[r,d] + scan1[r,d]).
__global__ __launch_bounds__(256, 4)
void coeffs_kernel(const float* __restrict__ scan,
                   const float* __restrict__ buf,
                   const float* __restrict__ cheby) {
    __shared__ float sData[BN][BD];         // [n][d]   16 KB
    __shared__ float sCheby[BN][2 * KBANDS]; // [n][2k] duplicated pairs, 16 KB

    const int chunk = blockIdx.y;
    const int d0 = blockIdx.x * BD;
    const int tid = threadIdx.x;
    const int tx = tid & 15;   // d group (0..15)
    const int ty = tid >> 4;   // k group (0..15), k = 4*ty..4*ty+3

    const float* scan1 = scan + (size_t)SEQ * D_MODEL;

    unsigned long long acc[4][4];
#pragma unroll
    for (int a = 0; a < 4; a++)
#pragma unroll
        for (int b = 0; b < 4; b++) acc[a][b] = 0ull;

    for (int n0 = 0; n0 < WWIN; n0 += BN) {
        // ---- load cheby tile, duplicated: sCheby[n][2k]=sCheby[n][2k+1]=cheby[k][n0+n]
        {
            const int k = tid >> 2;            // 0..63
            const int cb = (tid & 3) * 8;      // 0,8,16,24
            const float* src = cheby + k * WWIN + n0 + cb;
#pragma unroll
            for (int j = 0; j < 8; j++) {
                float v = src[j];
                sCheby[cb + j][2 * k] = v;
                sCheby[cb + j][2 * k + 1] = v;
            }
        }
        // ---- load data tile: rows lr=tid>>3 (0..31), cols (tid&7)*16 + 0..15
        {
            const int lr = tid >> 3;
            const int cb = (tid & 7) * 16;
            const int n = n0 + lr;
            if (chunk == 0 && n < STRIDE) {
                const float4* b4 = (const float4*)(buf + (size_t)(STRIDE + n) * D_MODEL + d0 + cb);
#pragma unroll
                for (int j = 0; j < 4; j++)
                    *(float4*)&sData[lr][cb + 4 * j] = b4[j];
            } else {
                const int g = (chunk - 1) * STRIDE + n;  // 0..8191
                const float4* a4 = (const float4*)(scan  + (size_t)g * D_MODEL + d0 + cb);
                const float4* b4 = (const float4*)(scan1 + (size_t)g * D_MODEL + d0 + cb);
#pragma unroll
                for (int j = 0; j < 4; j++) {
                    float4 va = a4[j], vb = b4[j];
                    float4 v = make_float4(0.5f * (va.x + vb.x), 0.5f * (va.y + vb.y),
                                           0.5f * (va.z + vb.z), 0.5f * (va.w + vb.w));
                    *(float4*)&sData[lr][cb + 4 * j] = v;
                }
            }
        }
        __syncthreads();

#pragma unroll 4
        for (int n = 0; n < BN; n++) {
            ulonglong2 cA = *(const ulonglong2*)&sCheby[n][ty * 8];      // k=4ty, 4ty+1
            ulonglong2 cB = *(const ulonglong2*)&sCheby[n][ty * 8 + 4];  // k=4ty+2, 4ty+3
            ulonglong2 b0 = *(const ulonglong2*)&sData[n][tx * 4];       // d pairs, seg 0
            ulonglong2 b1 = *(const ulonglong2*)&sData[n][64 + tx * 4];  // d pairs, seg 1
            fma2(acc[0][0], cA.x, b0.x); fma2(acc[0][1], cA.x, b0.y);
            fma2(acc[0][2], cA.x, b1.x); fma2(acc[0][3], cA.x, b1.y);
            fma2(acc[1][0], cA.y, b0.x); fma2(acc[1][1], cA.y, b0.y);
            fma2(acc[1][2], cA.y, b1.x); fma2(acc[1][3], cA.y, b1.y);
            fma2(acc[2][0], cB.x, b0.x); fma2(acc[2][1], cB.x, b0.y);
            fma2(acc[2][2], cB.x, b1.x); fma2(acc[2][3], cB.x, b1.y);
            fma2(acc[3][0], cB.y, b0.x); fma2(acc[3][1], cB.y, b0.y);
            fma2(acc[3][2], cB.y, b1.x); fma2(acc[3][3], cB.y, b1.y);
        }
        __syncthreads();
    }

    const float scale = 2.0f / (float)WWIN;  // 0.00390625
#pragma unroll
    for (int kk = 0; kk < 4; kk++) {
        const int k = ty * 4 + kk;
        const float s = scale * ((k == 0) ? 0.5f : 1.0f);
        float* orow = g_coeffs + (((size_t)chunk * KBANDS + k) << 11) + d0;
        float2 v0 = unpack2(acc[kk][0]);
        float2 v1 = unpack2(acc[kk][1]);
        float2 v2 = unpack2(acc[kk][2]);
        float2 v3 = unpack2(acc[kk][3]);
        *(float4*)&orow[tx * 4]      = make_float4(v0.x * s, v0.y * s, v1.x * s, v1.y * s);
        *(float4*)&orow[64 + tx * 4] = make_float4(v2.x * s, v2.y * s, v3.x * s, v3.y * s);
    }
}

// ---------------- block reduce helper ----------------------------------------
__device__ __forceinline__ float block_reduce_sum(float v) {
    __shared__ float sh[32];
    const int lane = threadIdx.x & 31;
    const int w = threadIdx.x >> 5;
#pragma unroll
    for (int o = 16; o > 0; o >>= 1) v += __shfl_down_sync(0xffffffffu, v, o);
    if (lane == 0) sh[w] = v;
    __syncthreads();
    const int nw = (blockDim.x + 31) >> 5;
    v = (threadIdx.x < (unsigned)nw) ? sh[threadIdx.x] : 0.0f;
    if (w == 0) {
#pragma unroll
        for (int o = 16; o > 0; o >>= 1) v += __shfl_down_sync(0xffffffffu, v, o);
    }
    return v;  // valid in thread 0
}

// ---------------- K2: per-(chunk,band) norms ---------------------------------
__global__ __launch_bounds__(256)
void norms_kernel() {
    const int ik = blockIdx.x;  // i*64 + k
    const float* row = g_coeffs + ((size_t)ik << 11);
    float s = 0.0f;
    for (int d = threadIdx.x; d < D_MODEL; d += 256) {
        float v = row[d];
        s = fmaf(v, v, s);
    }
    s = block_reduce_sum(s);
    if (threadIdx.x == 0) g_norms[ik] = fmaxf(sqrtf(s), 1e-12f);
}

// ---------------- K2b: cnorms EMA (tiny) -------------------------------------
__global__ void cnorms_kernel() {
    const int k = threadIdx.x;
    float c = 0.0f;
#pragma unroll
    for (int i = 0; i < NCHUNK; i++)
        c = 0.9f * c + 0.1f * g_norms[i * KBANDS + k];
    g_cnorms[k] = c;
}

// ---------------- K2c: final-step spectral delta -----------------------------
__global__ __launch_bounds__(256)
void delta_kernel(float* __restrict__ out) {
    const int k = blockIdx.x;
    const float* a = g_coeffs + (((size_t)31 * KBANDS + k) << 11);
    const float* b = g_coeffs + (((size_t)30 * KBANDS + k) << 11);
    float s = 0.0f;
    for (int d = threadIdx.x; d < D_MODEL; d += 256) {
        float v = a[d] - b[d];
        s = fmaf(v, v, s);
    }
    s = block_reduce_sum(s);
    if (threadIdx.x == 0) {
        float dv = sqrtf(s);
        g_delta[k] = dv;
        out[D_MODEL + k] = dv;   // delta at out[2048:2112]
    }
}

// ---------------- K3: EMA-weighted normalized coeff accumulation -------------
// T[k,d] = EMA over i of cn[i,k,d] with 0.1 weight:  t = 0.9 t + (0.1/norm) c
__global__ __launch_bounds__(128)
void t_kernel() {
    const int k = blockIdx.x;
    const int d = blockIdx.y * 128 + threadIdx.x;
    __shared__ float sInv[NCHUNK];
    if (threadIdx.x < NCHUNK)
        sInv[threadIdx.x] = 0.1f / g_norms[threadIdx.x * KBANDS + k];
    __syncthreads();
    float t = 0.0f;
#pragma unroll
    for (int i = 0; i < NCHUNK; i++)
        t = fmaf(sInv[i], g_coeffs[(((size_t)i * KBANDS + k) << 11) + d], 0.9f * t);
    g_T[((size_t)k << 11) + d] = t;
}

// ---------------- K4: bind -> vr, vi -----------------------------------------
__global__ __launch_bounds__(128)
void bind_kernel(const float* __restrict__ rr, const float* __restrict__ ri,
                 float* __restrict__ out) {
    const int d = blockIdx.x * 128 + threadIdx.x;
    float vr = 0.0f, vi = 0.0f;
#pragma unroll 8
    for (int k = 0; k < KBANDS; k++) {
        float t = g_T[((size_t)k << 11) + d];
        vr = fmaf(t, rr[((size_t)k << 11) + d], vr);
        vi = fmaf(t, ri[((size_t)k << 11) + d], vi);
    }
    g_vr[d] = vr;
    g_vi[d] = vi;
    out[D_MODEL + KBANDS + d] = vr;              // vr at out[2112:4160]
    out[2 * D_MODEL + KBANDS + d] = vi;          // vi at out[4160:6208]
}

// ---------------- K5: top-8 + ctx --------------------------------------------
__global__ __launch_bounds__(256)
void finalize_kernel(const float* __restrict__ rr, const float* __restrict__ ri,
                     const float* __restrict__ wb) {
    __shared__ int sTop[NRET];
    __shared__ float sC[NRET];
    if (threadIdx.x == 0) {
        float dl[KBANDS];
#pragma unroll
        for (int k = 0; k < KBANDS; k++) dl[k] = g_delta[k];
        for (int j = 0; j < NRET; j++) {
            int bi = 0;
            float bv = dl[0];
            for (int k = 1; k < KBANDS; k++)
                if (dl[k] > bv) { bv = dl[k]; bi = k; }   // strict >: first idx wins on ties
            sTop[j] = bi;
            float w = wb[bi];
            float sp = log1pf(expf(w));                   // softplus
            sC[j] = sp * fmaxf(g_cnorms[bi], 1e-12f);
            dl[bi] = -3.4e38f;
        }
    }
    __syncthreads();
    for (int d = threadIdx.x; d < D_MODEL; d += 256) {
        float vr = g_vr[d], vi = g_vi[d], c = 0.0f;
#pragma unroll
        for (int j = 0; j < NRET; j++) {
            int t = sTop[j];
            c = fmaf(sC[j], fmaf(vr, rr[((size_t)t << 11) + d],
                                 vi * ri[((size_t)t << 11) + d]), c);
        }
        g_ctx[d] = c;
    }
}

// ---------------- K6: output projection --------------------------------------
// out[d] = sigmoid(gate) * dot(ctx, Wp[d,:])
__global__ __launch_bounds__(128)
void proj_kernel(const float* __restrict__ wp, const float* __restrict__ gate,
                 float* __restrict__ out) {
    const int row = blockIdx.x;
    const float* w = wp + ((size_t)row << 11);
    float s = 0.0f;
    for (int e = threadIdx.x; e < D_MODEL; e += 128)
        s = fmaf(g_ctx[e], w[e], s);
    s = block_reduce_sum(s);
    if (threadIdx.x == 0) {
        float sig = 1.0f / (1.0f + expf(-gate[0]));
        out[row] = s * sig;
    }
}

// ---------------- launch ------------------------------------------------------
extern "C" void kernel_launch(void* const* d_in, const int* in_sizes, int n_in,
                              void* d_out, int out_size) {
    const float* scan  = (const float*)d_in[0];  // [2, 8192, 2048]
    const float* buf   = (const float*)d_in[1];  // [512, 2048]
    const float* rr    = (const float*)d_in[2];  // [64, 2048]
    const float* ri    = (const float*)d_in[3];  // [64, 2048]
    const float* wb    = (const float*)d_in[4];  // [64]
    const float* wp    = (const float*)d_in[5];  // [2048, 2048]
    const float* gate  = (const float*)d_in[6];  // [1]
    const float* cheby = (const float*)d_in[7];  // [64, 512]
    float* out = (float*)d_out;                  // [6208] = out|delta|vr|vi

    coeffs_kernel<<<dim3(D_MODEL / BD, NCHUNK), 256>>>(scan, buf, cheby);
    norms_kernel<<<NCHUNK * KBANDS, 256>>>();
    cnorms_kernel<<<1, KBANDS>>>();
    delta_kernel<<<KBANDS, 256>>>(out);
    t_kernel<<<dim3(KBANDS, D_MODEL / 128), 128>>>();
    bind_kernel<<<D_MODEL / 128, 128>>>(rr, ri, out);
    finalize_kernel<<<1, 256>>>(rr, ri, wb);
    proj_kernel<<<D_MODEL, 128>>>(wp, gate, out);
}

// round 2
// speedup vs baseline: 1.1362x; 1.1362x over previous
#include <cuda_runtime.h>
#include <cuda_bf16.h>
#include <math.h>
#include <stdint.h>

#define D_MODEL 2048
#define KBANDS  64
#define WWIN    512
#define STRIDE  256
#define NCHUNK  32
#define SEQ     8192
#define NRET    8
#define BD      128   // d-tile per block
#define KB      64    // n rows per stage

// ---------------- scratch ----------------------------------------------------
__device__ float g_coeffs[NCHUNK * KBANDS * D_MODEL];  // 16 MB
__device__ float g_norms[NCHUNK * KBANDS];
__device__ float g_delta[KBANDS];
__device__ float g_vr[D_MODEL];
__device__ float g_vi[D_MODEL];
__device__ float g_ctx[D_MODEL];

// ---------------- mma helpers ------------------------------------------------
__device__ __forceinline__ uint32_t saddr(const void* p) {
    return (uint32_t)__cvta_generic_to_shared(p);
}
__device__ __forceinline__ void ldsm4(uint32_t* r, uint32_t a) {
    asm volatile("ldmatrix.sync.aligned.m8n8.x4.shared.b16 {%0,%1,%2,%3}, [%4];"
                 : "=r"(r[0]), "=r"(r[1]), "=r"(r[2]), "=r"(r[3]) : "r"(a));
}
__device__ __forceinline__ void ldsm4t(uint32_t* r, uint32_t a) {
    asm volatile("ldmatrix.sync.aligned.m8n8.x4.trans.shared.b16 {%0,%1,%2,%3}, [%4];"
                 : "=r"(r[0]), "=r"(r[1]), "=r"(r[2]), "=r"(r[3]) : "r"(a));
}
__device__ __forceinline__ void mma16816(float* c, const uint32_t* a, uint32_t b0, uint32_t b1) {
    asm volatile("mma.sync.aligned.m16n8k16.row.col.f32.bf16.bf16.f32 "
                 "{%0,%1,%2,%3},{%4,%5,%6,%7},{%8,%9},{%0,%1,%2,%3};"
                 : "+f"(c[0]), "+f"(c[1]), "+f"(c[2]), "+f"(c[3])
                 : "r"(a[0]), "r"(a[1]), "r"(a[2]), "r"(a[3]), "r"(b0), "r"(b1));
}
// split fp32 pair -> (hi bf16x2, lo bf16x2), lo = x - float(hi)
__device__ __forceinline__ void split2(float a, float b, uint32_t& hi, uint32_t& lo) {
    __nv_bfloat162 h = __floats2bfloat162_rn(a, b);
    hi = *(uint32_t*)&h;
    float ha = __uint_as_float(hi << 16);
    float hb = __uint_as_float(hi & 0xFFFF0000u);
    __nv_bfloat162 l = __floats2bfloat162_rn(a - ha, b - hb);
    lo = *(uint32_t*)&l;
}

// ---------------- K1: fused h_mean + Chebyshev GEMM via bf16-split HMMA ------
// coeffs[i,k,d] = (2/W) * sum_n cheby[k,n] * data_i[n,d], row k=0 halved.
// A = cheby [64 x 512] (M=band, K=n), B = data [512 x 128-tile] (K=n, N=d).
__global__ __launch_bounds__(256)
void coeffs_mma(const float* __restrict__ scan,
                const float* __restrict__ buf,
                const float* __restrict__ cheby) {
    __shared__ __align__(16) __nv_bfloat16 sDhi[KB * BD];   // 16 KB
    __shared__ __align__(16) __nv_bfloat16 sDlo[KB * BD];   // 16 KB
    __shared__ __align__(16) __nv_bfloat16 sAhi[64 * 64];   // 8 KB
    __shared__ __align__(16) __nv_bfloat16 sAlo[64 * 64];   // 8 KB  (total 48 KB)

    const int ci = blockIdx.y;           // chunk
    const int d0 = blockIdx.x * BD;
    const int tid = threadIdx.x;
    const int lane = tid & 31;
    const int warp = tid >> 5;
    const int wm = warp >> 1;            // 0..3 -> band rows [wm*16, +16)
    const int wn = warp & 1;             // 0..1 -> d cols [wn*64, +64)
    const float* scan1 = scan + (size_t)SEQ * D_MODEL;

    float acc[8][4];
#pragma unroll
    for (int f = 0; f < 8; f++)
#pragma unroll
        for (int q = 0; q < 4; q++) acc[f][q] = 0.0f;

    for (int s = 0; s < 8; s++) {        // 8 stages of 64 n-rows
        __syncthreads();
        // ---- fill A tile (cheby[band][s*64 .. +64)), hi/lo split, swizzled
        {
            const int band = tid >> 2;
            const int c0 = (tid & 3) * 16;
            const float* src = cheby + band * WWIN + s * 64 + c0;
            uint32_t hi[8], lo[8];
#pragma unroll
            for (int j = 0; j < 8; j++) split2(src[2 * j], src[2 * j + 1], hi[j], lo[j]);
            const int seg0 = c0 >> 3;
            const int sw0 = (seg0 ^ (band & 7)) << 3;
            const int sw1 = ((seg0 + 1) ^ (band & 7)) << 3;
            *(uint4*)&sAhi[band * 64 + sw0] = make_uint4(hi[0], hi[1], hi[2], hi[3]);
            *(uint4*)&sAhi[band * 64 + sw1] = make_uint4(hi[4], hi[5], hi[6], hi[7]);
            *(uint4*)&sAlo[band * 64 + sw0] = make_uint4(lo[0], lo[1], lo[2], lo[3]);
            *(uint4*)&sAlo[band * 64 + sw1] = make_uint4(lo[4], lo[5], lo[6], lo[7]);
        }
        // ---- fill data tile: row r = n-index within stage, 128 d cols
        {
            const int r = tid >> 2;
            const int ng = s * 64 + r;                 // n in window (0..511)
            const float* p0;
            const float* p1 = nullptr;
            if (ci == 0 && ng < STRIDE) {
                p0 = buf + (size_t)(STRIDE + ng) * D_MODEL + d0;
            } else {
                const int g = (ci - 1) * STRIDE + ng;  // hmean row
                p0 = scan + (size_t)g * D_MODEL + d0;
                p1 = scan1 + (size_t)g * D_MODEL + d0;
            }
#pragma unroll
            for (int jj = 0; jj < 4; jj++) {
                const int seg = (tid & 3) * 4 + jj;    // 16B chunk 0..15
                const float4 x0 = *(const float4*)(p0 + seg * 8);
                const float4 x1 = *(const float4*)(p0 + seg * 8 + 4);
                float h[8] = {x0.x, x0.y, x0.z, x0.w, x1.x, x1.y, x1.z, x1.w};
                if (p1) {
                    const float4 y0 = *(const float4*)(p1 + seg * 8);
                    const float4 y1 = *(const float4*)(p1 + seg * 8 + 4);
                    h[0] = 0.5f * (h[0] + y0.x); h[1] = 0.5f * (h[1] + y0.y);
                    h[2] = 0.5f * (h[2] + y0.z); h[3] = 0.5f * (h[3] + y0.w);
                    h[4] = 0.5f * (h[4] + y1.x); h[5] = 0.5f * (h[5] + y1.y);
                    h[6] = 0.5f * (h[6] + y1.z); h[7] = 0.5f * (h[7] + y1.w);
                }
                uint32_t hi[4], lo[4];
#pragma unroll
                for (int j = 0; j < 4; j++) split2(h[2 * j], h[2 * j + 1], hi[j], lo[j]);
                const int sw = (seg ^ (r & 7)) << 3;
                *(uint4*)&sDhi[r * BD + sw] = make_uint4(hi[0], hi[1], hi[2], hi[3]);
                *(uint4*)&sDlo[r * BD + sw] = make_uint4(lo[0], lo[1], lo[2], lo[3]);
            }
        }
        __syncthreads();

#pragma unroll
        for (int kk = 0; kk < 4; kk++) {   // 4 k16 substeps per stage
            uint32_t ah[4], al[4];
            {
                const int row = wm * 16 + (lane & 15);
                const int seg = kk * 2 + (lane >> 4);
                const int off = row * 64 + ((seg ^ (row & 7)) << 3);
                ldsm4(ah, saddr(&sAhi[off]));
                ldsm4(al, saddr(&sAlo[off]));
            }
            uint32_t bh[16], bl[16];
#pragma unroll
            for (int g = 0; g < 4; g++) {
                const int rn = kk * 16 + (lane & 15);
                const int seg = wn * 8 + g * 2 + (lane >> 4);
                const int off = rn * BD + ((seg ^ (rn & 7)) << 3);
                ldsm4t(&bh[4 * g], saddr(&sDhi[off]));
                ldsm4t(&bl[4 * g], saddr(&sDlo[off]));
            }
            // pass 1: hi*hi
#pragma unroll
            for (int g = 0; g < 4; g++) {
                mma16816(acc[2 * g],     ah, bh[4 * g],     bh[4 * g + 1]);
                mma16816(acc[2 * g + 1], ah, bh[4 * g + 2], bh[4 * g + 3]);
            }
            // pass 2: hi*lo
#pragma unroll
            for (int g = 0; g < 4; g++) {
                mma16816(acc[2 * g],     ah, bl[4 * g],     bl[4 * g + 1]);
                mma16816(acc[2 * g + 1], ah, bl[4 * g + 2], bl[4 * g + 3]);
            }
            // pass 3: lo*hi
#pragma unroll
            for (int g = 0; g < 4; g++) {
                mma16816(acc[2 * g],     al, bh[4 * g],     bh[4 * g + 1]);
                mma16816(acc[2 * g + 1], al, bh[4 * g + 2], bh[4 * g + 3]);
            }
        }
    }

    // ---- epilogue: scale + store
    const float sc = 2.0f / (float)WWIN;
    const int row = wm * 16 + (lane >> 2);
    const float s0 = (row == 0) ? sc * 0.5f : sc;
#pragma unroll
    for (int f = 0; f < 8; f++) {
        const int col = d0 + wn * 64 + f * 8 + (lane & 3) * 2;
        float* dst = g_coeffs + (((size_t)(ci * 64 + row)) << 11) + col;
        *(float2*)dst = make_float2(acc[f][0] * s0, acc[f][1] * s0);
        *(float2*)(dst + (8 << 11)) = make_float2(acc[f][2] * sc, acc[f][3] * sc);  // row+8 != 0
    }
}

// ---------------- K2: norms (+ final delta fused, + zero vr/vi) --------------
__global__ __launch_bounds__(256)
void norms2_kernel() {
    __shared__ float sh[32];
    const int ik = blockIdx.x;
    const int t = threadIdx.x;
    const int i = ik >> 6, k = ik & 63;

    if (ik < 8) g_vr[ik * 256 + t] = 0.0f;
    else if (ik < 16) g_vi[(ik - 8) * 256 + t] = 0.0f;

    const float4* row = (const float4*)(g_coeffs + ((size_t)ik << 11));
    const bool last = (i == NCHUNK - 1);
    const float4* prev = (const float4*)(g_coeffs + (((size_t)((NCHUNK - 2) * 64 + k)) << 11));
    float s = 0.0f, dl = 0.0f;
#pragma unroll
    for (int it = 0; it < 2; it++) {
        float4 v = row[t + 256 * it];
        s += v.x * v.x + v.y * v.y + v.z * v.z + v.w * v.w;
        if (last) {
            float4 p = prev[t + 256 * it];
            float a = v.x - p.x, b = v.y - p.y, c = v.z - p.z, d = v.w - p.w;
            dl += a * a + b * b + c * c + d * d;
        }
    }
    // reduce s
    const int lane = t & 31, w = t >> 5;
#pragma unroll
    for (int o = 16; o > 0; o >>= 1) s += __shfl_down_sync(0xffffffffu, s, o);
    if (lane == 0) sh[w] = s;
    __syncthreads();
    if (t == 0) {
        float tot = 0.0f;
#pragma unroll
        for (int j = 0; j < 8; j++) tot += sh[j];
        g_norms[ik] = fmaxf(sqrtf(tot), 1e-12f);
    }
    if (last) {
        __syncthreads();
#pragma unroll
        for (int o = 16; o > 0; o >>= 1) dl += __shfl_down_sync(0xffffffffu, dl, o);
        if (lane == 0) sh[w] = dl;
        __syncthreads();
        if (t == 0) {
            float tot = 0.0f;
#pragma unroll
            for (int j = 0; j < 8; j++) tot += sh[j];
            g_delta[k] = sqrtf(tot);
        }
    }
}

// ---------------- K3: fused T-EMA + bind (atomic accumulation into vr/vi) ----
// vr[d] = sum_{i,k} (0.1*0.9^{31-i}/norm[i,k]) * coeffs[i,k,d] * rr[k,d]
__global__ __launch_bounds__(256)
void tbind_kernel(const float* __restrict__ rr, const float* __restrict__ ri) {
    const int i = blockIdx.x;
    const int d = (blockIdx.y << 8) + threadIdx.x;
    __shared__ float winv[64];
    if (threadIdx.x < 64) {
        float w = 0.1f;
        for (int j = i; j < NCHUNK - 1; j++) w *= 0.9f;
        winv[threadIdx.x] = w / g_norms[(i << 6) + threadIdx.x];
    }
    __syncthreads();
    float vr = 0.0f, vi = 0.0f;
#pragma unroll 8
    for (int k = 0; k < 64; k++) {
        const float c = g_coeffs[(((size_t)((i << 6) | k)) << 11) + d];
        const float wv = winv[k] * c;
        vr = fmaf(wv, rr[((size_t)k << 11) + d], vr);
        vi = fmaf(wv, ri[((size_t)k << 11) + d], vi);
    }
    atomicAdd(&g_vr[d], vr);
    atomicAdd(&g_vi[d], vi);
}

// ---------------- K4: cnorms EMA + top-8 + ctx + out(delta,vr,vi) ------------
__global__ __launch_bounds__(256)
void finalize_kernel(const float* __restrict__ rr, const float* __restrict__ ri,
                     const float* __restrict__ wb, float* __restrict__ out) {
    __shared__ float sDelta[64], sCn[64], sC[NRET];
    __shared__ int sTop[NRET];
    const int t = threadIdx.x;
    if (t < 64) {
        float c = 0.0f;
        for (int i = 0; i < NCHUNK; i++) c = 0.9f * c + 0.1f * g_norms[(i << 6) + t];
        sCn[t] = c;
        const float dv = g_delta[t];
        sDelta[t] = dv;
        out[D_MODEL + t] = dv;
    }
    __syncthreads();
    if (t == 0) {
        for (int j = 0; j < NRET; j++) {
            int bi = 0;
            float bv = sDelta[0];
            for (int k = 1; k < 64; k++)
                if (sDelta[k] > bv) { bv = sDelta[k]; bi = k; }
            sTop[j] = bi;
            sC[j] = log1pf(expf(wb[bi])) * fmaxf(sCn[bi], 1e-12f);
            sDelta[bi] = -3.4e38f;
        }
    }
    __syncthreads();
    for (int d = t; d < D_MODEL; d += 256) {
        const float vr = g_vr[d], vi = g_vi[d];
        float c = 0.0f;
#pragma unroll
        for (int j = 0; j < NRET; j++) {
            const int tp = sTop[j];
            c = fmaf(sC[j], fmaf(vr, rr[((size_t)tp << 11) + d], vi * ri[((size_t)tp << 11) + d]), c);
        }
        g_ctx[d] = c;
        out[D_MODEL + KBANDS + d] = vr;
        out[2 * D_MODEL + KBANDS + d] = vi;
    }
}

// ---------------- K5: output projection --------------------------------------
__global__ __launch_bounds__(128)
void proj_kernel(const float* __restrict__ wp, const float* __restrict__ gate,
                 float* __restrict__ out) {
    __shared__ float sh[4];
    const int row = blockIdx.x;
    const int t = threadIdx.x;
    const float4* w = (const float4*)(wp + ((size_t)row << 11));
    const float4* cx = (const float4*)g_ctx;
    float s = 0.0f;
#pragma unroll
    for (int it = 0; it < 4; it++) {
        float4 a = w[t + 128 * it], b = cx[t + 128 * it];
        s += a.x * b.x + a.y * b.y + a.z * b.z + a.w * b.w;
    }
#pragma unroll
    for (int o = 16; o > 0; o >>= 1) s += __shfl_down_sync(0xffffffffu, s, o);
    if ((t & 31) == 0) sh[t >> 5] = s;
    __syncthreads();
    if (t == 0) {
        const float tot = sh[0] + sh[1] + sh[2] + sh[3];
        out[row] = tot * (1.0f / (1.0f + expf(-gate[0])));
    }
}

// ---------------- launch ------------------------------------------------------
extern "C" void kernel_launch(void* const* d_in, const int* in_sizes, int n_in,
                              void* d_out, int out_size) {
    const float* scan  = (const float*)d_in[0];  // [2, 8192, 2048]
    const float* buf   = (const float*)d_in[1];  // [512, 2048]
    const float* rr    = (const float*)d_in[2];  // [64, 2048]
    const float* ri    = (const float*)d_in[3];  // [64, 2048]
    const float* wb    = (const float*)d_in[4];  // [64]
    const float* wp    = (const float*)d_in[5];  // [2048, 2048]
    const float* gate  = (const float*)d_in[6];  // [1]
    const float* cheby = (const float*)d_in[7];  // [64, 512]
    float* out = (float*)d_out;                  // [6208] = out|delta|vr|vi

    coeffs_mma<<<dim3(D_MODEL / BD, NCHUNK), 256>>>(scan, buf, cheby);
    norms2_kernel<<<NCHUNK * KBANDS, 256>>>();
    tbind_kernel<<<dim3(NCHUNK, D_MODEL / 256), 256>>>(rr, ri);
    finalize_kernel<<<1, 256>>>(rr, ri, wb, out);
    proj_kernel<<<D_MODEL, 128>>>(wp, gate, out);
}

// round 3
// speedup vs baseline: 2.4284x; 2.1374x over previous
#include <cuda_runtime.h>
#include <cuda_bf16.h>
#include <math.h>
#include <stdint.h>

#define D_MODEL 2048
#define KBANDS  64
#define WWIN    512
#define STRIDE  256
#define NCHUNK  32
#define SEQ     8192
#define NRET    8
#define NDATA   33    // data chunks: j=0 is buf[256:512], j=1..32 are chunks 0..31

// ---------------- scratch ----------------------------------------------------
__device__ float g_P[NDATA * KBANDS * D_MODEL];   // A_L @ data_j   (17 MB)
__device__ float g_Q[NDATA * KBANDS * D_MODEL];   // A_R @ data_j   (17 MB)
__device__ float g_norms[NCHUNK * KBANDS];
__device__ float g_delta[KBANDS];
__device__ float g_vr[D_MODEL];
__device__ float g_vi[D_MODEL];
__device__ float g_ctx[D_MODEL];
__device__ int   g_top[NRET];
__device__ float g_cw[NRET];

// ---------------- mma helpers ------------------------------------------------
__device__ __forceinline__ uint32_t saddr(const void* p) {
    return (uint32_t)__cvta_generic_to_shared(p);
}
__device__ __forceinline__ void ldsm4(uint32_t* r, uint32_t a) {
    asm volatile("ldmatrix.sync.aligned.m8n8.x4.shared.b16 {%0,%1,%2,%3}, [%4];"
                 : "=r"(r[0]), "=r"(r[1]), "=r"(r[2]), "=r"(r[3]) : "r"(a));
}
__device__ __forceinline__ void ldsm4t(uint32_t* r, uint32_t a) {
    asm volatile("ldmatrix.sync.aligned.m8n8.x4.trans.shared.b16 {%0,%1,%2,%3}, [%4];"
                 : "=r"(r[0]), "=r"(r[1]), "=r"(r[2]), "=r"(r[3]) : "r"(a));
}
__device__ __forceinline__ void mma16816(float* c, const uint32_t* a, uint32_t b0, uint32_t b1) {
    asm volatile("mma.sync.aligned.m16n8k16.row.col.f32.bf16.bf16.f32 "
                 "{%0,%1,%2,%3},{%4,%5,%6,%7},{%8,%9},{%0,%1,%2,%3};"
                 : "+f"(c[0]), "+f"(c[1]), "+f"(c[2]), "+f"(c[3])
                 : "r"(a[0]), "r"(a[1]), "r"(a[2]), "r"(a[3]), "r"(b0), "r"(b1));
}
__device__ __forceinline__ void split2(float a, float b, uint32_t& hi, uint32_t& lo) {
    __nv_bfloat162 h = __floats2bfloat162_rn(a, b);
    hi = *(uint32_t*)&h;
    float ha = __uint_as_float(hi << 16);
    float hb = __uint_as_float(hi & 0xFFFF0000u);
    __nv_bfloat162 l = __floats2bfloat162_rn(a - ha, b - hb);
    lo = *(uint32_t*)&l;
}

// ---------------- K1: P/Q GEMM -----------------------------------------------
// Stacked A' [128 x 256]: row m<64 -> cheby[m][0:256]; m>=64 -> cheby[m-64][256:512].
// B = data_j [256 x 128 d-tile] (hmean or buf), K staged 32 at a time.
// Output: rows 0..63 -> P[j], rows 64..127 -> Q[j], scaled by 2/W (band 0 halved).
__global__ __launch_bounds__(256, 2)
void pq_mma(const float* __restrict__ scan,
            const float* __restrict__ buf,
            const float* __restrict__ cheby) {
    __shared__ __align__(16) __nv_bfloat16 sA[128 * 64];     // hi segs 0-3, lo segs 4-7 (16 KB)
    __shared__ __align__(16) __nv_bfloat16 sDhi[32 * 128];   // 8 KB
    __shared__ __align__(16) __nv_bfloat16 sDlo[32 * 128];   // 8 KB

    const int j = blockIdx.y;
    const int d0 = blockIdx.x * 128;
    const int tid = threadIdx.x;
    const int lane = tid & 31;
    const int warp = tid >> 5;
    const int wy = warp >> 1;   // 0..3 : m-range wy*32
    const int wx = warp & 1;    // 0..1 : d-range wx*64
    const float* scan1 = scan + (size_t)SEQ * D_MODEL;

    float acc[2][8][4];
#pragma unroll
    for (int a = 0; a < 2; a++)
#pragma unroll
        for (int f = 0; f < 8; f++)
#pragma unroll
            for (int q = 0; q < 4; q++) acc[a][f][q] = 0.0f;

    for (int s = 0; s < 8; s++) {        // 8 stages of K=32
        __syncthreads();
        // ---- A' tile fill: thread t -> row t>>1, k-half (t&1)*16
        {
            const int row = tid >> 1;
            const int kh = tid & 1;
            const int band = row & 63;
            const int koff = ((row >> 6) ? 256 : 0) + s * 32 + kh * 16;
            const float* src = cheby + band * WWIN + koff;
            uint32_t hi[8], lo[8];
#pragma unroll
            for (int q = 0; q < 4; q++) {
                float4 v = *(const float4*)(src + 4 * q);
                split2(v.x, v.y, hi[2 * q], lo[2 * q]);
                split2(v.z, v.w, hi[2 * q + 1], lo[2 * q + 1]);
            }
            const int s0 = kh * 2;
            const int r7 = row & 7;
            __nv_bfloat16* rbase = sA + row * 64;
            *(uint4*)(rbase + (((s0    ) ^ r7) << 3)) = make_uint4(hi[0], hi[1], hi[2], hi[3]);
            *(uint4*)(rbase + (((s0 + 1) ^ r7) << 3)) = make_uint4(hi[4], hi[5], hi[6], hi[7]);
            *(uint4*)(rbase + (((s0 + 4) ^ r7) << 3)) = make_uint4(lo[0], lo[1], lo[2], lo[3]);
            *(uint4*)(rbase + (((s0 + 5) ^ r7) << 3)) = make_uint4(lo[4], lo[5], lo[6], lo[7]);
        }
        // ---- D tile fill: thread t -> n-row t>>3 (0..31), 16 d cols at (t&7)*16
        {
            const int r = tid >> 3;
            const int sp = tid & 7;
            const int n = s * 32 + r;                  // row within this chunk (0..255)
            float h[16];
            if (j == 0) {
                const float* p0 = buf + (size_t)(STRIDE + n) * D_MODEL + d0 + sp * 16;
#pragma unroll
                for (int q = 0; q < 4; q++) {
                    float4 v = *(const float4*)(p0 + 4 * q);
                    h[4 * q] = v.x; h[4 * q + 1] = v.y; h[4 * q + 2] = v.z; h[4 * q + 3] = v.w;
                }
            } else {
                const size_t g = (size_t)((j - 1) * STRIDE + n) * D_MODEL + d0 + sp * 16;
                const float* p0 = scan + g;
                const float* p1 = scan1 + g;
#pragma unroll
                for (int q = 0; q < 4; q++) {
                    float4 a = *(const float4*)(p0 + 4 * q);
                    float4 b = *(const float4*)(p1 + 4 * q);
                    h[4 * q]     = 0.5f * (a.x + b.x);
                    h[4 * q + 1] = 0.5f * (a.y + b.y);
                    h[4 * q + 2] = 0.5f * (a.z + b.z);
                    h[4 * q + 3] = 0.5f * (a.w + b.w);
                }
            }
            uint32_t hi[8], lo[8];
#pragma unroll
            for (int q = 0; q < 8; q++) split2(h[2 * q], h[2 * q + 1], hi[q], lo[q]);
            const int r7 = r & 7;
            const int s0 = sp * 2;
            *(uint4*)(sDhi + r * 128 + (((s0    ) ^ r7) << 3)) = make_uint4(hi[0], hi[1], hi[2], hi[3]);
            *(uint4*)(sDhi + r * 128 + (((s0 + 1) ^ r7) << 3)) = make_uint4(hi[4], hi[5], hi[6], hi[7]);
            *(uint4*)(sDlo + r * 128 + (((s0    ) ^ r7) << 3)) = make_uint4(lo[0], lo[1], lo[2], lo[3]);
            *(uint4*)(sDlo + r * 128 + (((s0 + 1) ^ r7) << 3)) = make_uint4(lo[4], lo[5], lo[6], lo[7]);
        }
        __syncthreads();

#pragma unroll
        for (int kk = 0; kk < 2; kk++) {
            uint32_t ah[2][4], al[2][4];
#pragma unroll
            for (int t16 = 0; t16 < 2; t16++) {
                const int row = wy * 32 + t16 * 16 + (lane & 15);
                const int sg = kk * 2 + (lane >> 4);
                const int r7 = row & 7;
                ldsm4(ah[t16], saddr(sA + row * 64 + (((sg    ) ^ r7) << 3)));
                ldsm4(al[t16], saddr(sA + row * 64 + (((sg + 4) ^ r7) << 3)));
            }
#pragma unroll
            for (int g = 0; g < 4; g++) {
                const int rn = kk * 16 + (lane & 15);
                const int sg = wx * 8 + g * 2 + (lane >> 4);
                const int off = rn * 128 + ((sg ^ (rn & 7)) << 3);
                uint32_t bh[4], bl[4];
                ldsm4t(bh, saddr(sDhi + off));
                ldsm4t(bl, saddr(sDlo + off));
#pragma unroll
                for (int t16 = 0; t16 < 2; t16++) {
                    mma16816(acc[t16][2 * g],     ah[t16], bh[0], bh[1]);
                    mma16816(acc[t16][2 * g + 1], ah[t16], bh[2], bh[3]);
                    mma16816(acc[t16][2 * g],     ah[t16], bl[0], bl[1]);
                    mma16816(acc[t16][2 * g + 1], ah[t16], bl[2], bl[3]);
                    mma16816(acc[t16][2 * g],     al[t16], bh[0], bh[1]);
                    mma16816(acc[t16][2 * g + 1], al[t16], bh[2], bh[3]);
                }
            }
        }
    }

    // ---- epilogue
    const float sc = 2.0f / (float)WWIN;
#pragma unroll
    for (int t16 = 0; t16 < 2; t16++) {
        const int m = wy * 32 + t16 * 16 + (lane >> 2);
        const float s0 = (m == 0 || m == 64) ? sc * 0.5f : sc;
        float* base = (m < 64) ? (g_P + (((size_t)(j * 64 + m)) << 11))
                               : (g_Q + (((size_t)(j * 64 + (m - 64))) << 11));
#pragma unroll
        for (int f = 0; f < 8; f++) {
            const int col = d0 + wx * 64 + f * 8 + (lane & 3) * 2;
            *(float2*)(base + col) = make_float2(acc[t16][f][0] * s0, acc[t16][f][1] * s0);
            *(float2*)(base + col + (8 << 11)) = make_float2(acc[t16][f][2] * sc, acc[t16][f][3] * sc);
        }
    }
}

// ---------------- K2: norms (+ final delta, + zero vr/vi) --------------------
// coeffs_i[k][d] = P[i][k][d] + Q[i+1][k][d]
__global__ __launch_bounds__(256)
void norms2_kernel() {
    __shared__ float sh[8];
    const int ik = blockIdx.x;
    const int t = threadIdx.x;
    const int i = ik >> 6, k = ik & 63;

    if (ik < 8) g_vr[ik * 256 + t] = 0.0f;
    else if (ik < 16) g_vi[(ik - 8) * 256 + t] = 0.0f;

    const float4* p = (const float4*)(g_P + (((size_t)(i * 64 + k)) << 11));
    const float4* q = (const float4*)(g_Q + (((size_t)((i + 1) * 64 + k)) << 11));
    const bool last = (i == NCHUNK - 1);
    const float4* pp = (const float4*)(g_P + (((size_t)(30 * 64 + k)) << 11));
    const float4* qp = (const float4*)(g_Q + (((size_t)(31 * 64 + k)) << 11));
    float s = 0.0f, dl = 0.0f;
#pragma unroll
    for (int it = 0; it < 2; it++) {
        float4 a = p[t + 256 * it], b = q[t + 256 * it];
        float cx = a.x + b.x, cy = a.y + b.y, cz = a.z + b.z, cw = a.w + b.w;
        s += cx * cx + cy * cy + cz * cz + cw * cw;
        if (last) {
            float4 c = pp[t + 256 * it], d = qp[t + 256 * it];
            float ex = cx - c.x - d.x, ey = cy - c.y - d.y;
            float ez = cz - c.z - d.z, ew = cw - c.w - d.w;
            dl += ex * ex + ey * ey + ez * ez + ew * ew;
        }
    }
    const int lane = t & 31, w = t >> 5;
#pragma unroll
    for (int o = 16; o > 0; o >>= 1) s += __shfl_down_sync(0xffffffffu, s, o);
    if (lane == 0) sh[w] = s;
    __syncthreads();
    if (t == 0) {
        float tot = 0.0f;
#pragma unroll
        for (int jj = 0; jj < 8; jj++) tot += sh[jj];
        g_norms[ik] = fmaxf(sqrtf(tot), 1e-12f);
    }
    if (last) {
        __syncthreads();
#pragma unroll
        for (int o = 16; o > 0; o >>= 1) dl += __shfl_down_sync(0xffffffffu, dl, o);
        if (lane == 0) sh[w] = dl;
        __syncthreads();
        if (t == 0) {
            float tot = 0.0f;
#pragma unroll
            for (int jj = 0; jj < 8; jj++) tot += sh[jj];
            g_delta[k] = sqrtf(tot);
        }
    }
}

// ---------------- K3: fused T-EMA + bind -------------------------------------
__global__ __launch_bounds__(256)
void tbind_kernel(const float* __restrict__ rr, const float* __restrict__ ri) {
    const int i = blockIdx.x;
    const int d = (blockIdx.y << 8) + threadIdx.x;
    __shared__ float winv[64];
    if (threadIdx.x < 64) {
        float w = 0.1f;
        for (int jj = i; jj < NCHUNK - 1; jj++) w *= 0.9f;
        winv[threadIdx.x] = w / g_norms[(i << 6) + threadIdx.x];
    }
    __syncthreads();
    float vr = 0.0f, vi = 0.0f;
#pragma unroll 8
    for (int k = 0; k < 64; k++) {
        const float c = g_P[(((size_t)((i << 6) | k)) << 11) + d] +
                        g_Q[(((size_t)(((i + 1) << 6) | k)) << 11) + d];
        const float wv = winv[k] * c;
        vr = fmaf(wv, rr[((size_t)k << 11) + d], vr);
        vi = fmaf(wv, ri[((size_t)k << 11) + d], vi);
    }
    atomicAdd(&g_vr[d], vr);
    atomicAdd(&g_vi[d], vi);
}

// ---------------- K4a: cnorms EMA + top-8 scalars ----------------------------
__global__ void scalars_kernel(const float* __restrict__ wb, float* __restrict__ out) {
    __shared__ float sDelta[64], sCn[64];
    const int t = threadIdx.x;  // 64 threads
    float c = 0.0f;
    for (int i = 0; i < NCHUNK; i++) c = 0.9f * c + 0.1f * g_norms[(i << 6) + t];
    sCn[t] = c;
    const float dv = g_delta[t];
    sDelta[t] = dv;
    out[D_MODEL + t] = dv;
    __syncthreads();
    if (t == 0) {
        for (int jj = 0; jj < NRET; jj++) {
            int bi = 0;
            float bv = sDelta[0];
            for (int k = 1; k < 64; k++)
                if (sDelta[k] > bv) { bv = sDelta[k]; bi = k; }
            g_top[jj] = bi;
            g_cw[jj] = log1pf(expf(wb[bi])) * fmaxf(sCn[bi], 1e-12f);
            sDelta[bi] = -3.4e38f;
        }
    }
}

// ---------------- K4b: ctx + vr/vi outputs -----------------------------------
__global__ __launch_bounds__(128)
void ctx_kernel(const float* __restrict__ rr, const float* __restrict__ ri,
                float* __restrict__ out) {
    const int d = (blockIdx.x << 7) + threadIdx.x;
    const float vr = g_vr[d], vi = g_vi[d];
    float c = 0.0f;
#pragma unroll
    for (int jj = 0; jj < NRET; jj++) {
        const int tp = g_top[jj];
        c = fmaf(g_cw[jj], fmaf(vr, rr[((size_t)tp << 11) + d], vi * ri[((size_t)tp << 11) + d]), c);
    }
    g_ctx[d] = c;
    out[D_MODEL + KBANDS + d] = vr;
    out[2 * D_MODEL + KBANDS + d] = vi;
}

// ---------------- K5: output projection --------------------------------------
__global__ __launch_bounds__(128)
void proj_kernel(const float* __restrict__ wp, const float* __restrict__ gate,
                 float* __restrict__ out) {
    __shared__ float sh[4];
    const int row = blockIdx.x;
    const int t = threadIdx.x;
    const float4* w = (const float4*)(wp + ((size_t)row << 11));
    const float4* cx = (const float4*)g_ctx;
    float s = 0.0f;
#pragma unroll
    for (int it = 0; it < 4; it++) {
        float4 a = w[t + 128 * it], b = cx[t + 128 * it];
        s += a.x * b.x + a.y * b.y + a.z * b.z + a.w * b.w;
    }
#pragma unroll
    for (int o = 16; o > 0; o >>= 1) s += __shfl_down_sync(0xffffffffu, s, o);
    if ((t & 31) == 0) sh[t >> 5] = s;
    __syncthreads();
    if (t == 0) {
        const float tot = sh[0] + sh[1] + sh[2] + sh[3];
        out[row] = tot * (1.0f / (1.0f + expf(-gate[0])));
    }
}

// ---------------- launch ------------------------------------------------------
extern "C" void kernel_launch(void* const* d_in, const int* in_sizes, int n_in,
                              void* d_out, int out_size) {
    const float* scan  = (const float*)d_in[0];
    const float* buf   = (const float*)d_in[1];
    const float* rr    = (const float*)d_in[2];
    const float* ri    = (const float*)d_in[3];
    const float* wb    = (const float*)d_in[4];
    const float* wp    = (const float*)d_in[5];
    const float* gate  = (const float*)d_in[6];
    const float* cheby = (const float*)d_in[7];
    float* out = (float*)d_out;

    pq_mma<<<dim3(16, NDATA), 256>>>(scan, buf, cheby);
    norms2_kernel<<<NCHUNK * KBANDS, 256>>>();
    tbind_kernel<<<dim3(NCHUNK, 8), 256>>>(rr, ri);
    scalars_kernel<<<1, 64>>>(wb, out);
    ctx_kernel<<<16, 128>>>(rr, ri, out);
    proj_kernel<<<D_MODEL, 128>>>(wp, gate, out);
}